// round 15
// baseline (speedup 1.0000x reference)
#include <cuda_runtime.h>
#include <cuda_fp16.h>
#include <math.h>
#include <stdint.h>

#define BBATCH 16
#define NPTS   4096
#define THREADS 512
#define RPT 4
#define SPLIT 2
#define HALF_PTS (NPTS / SPLIT)            // 2048 targets per block
#define ROWS_PER_BLOCK (THREADS * RPT)     // 2048
#define ROW_TILES (NPTS / ROWS_PER_BLOCK)  // 2
#define NPAIRS (2 * BBATCH * ROW_TILES)    // 64 merge pairs
#define GSIZE 64
#define NGROUPS (HALF_PTS / GSIZE)         // 32 -> u32 mask
#define EPSF 1e-12f

// Dynamic smem: fp32 SoA (exact replay) + fp16 SoA (candidate pass)
#define SM_SX 0
#define SM_SY (SM_SX + HALF_PTS * 4)
#define SM_SZ (SM_SY + HALF_PTS * 4)
#define SM_SW (SM_SZ + HALF_PTS * 4)
#define SM_HX (SM_SW + HALF_PTS * 4)
#define SM_HY (SM_HX + HALF_PTS * 2)
#define SM_HZ (SM_HY + HALF_PTS * 2)
#define SM_HW (SM_HZ + HALF_PTS * 2)
#define SM_TOTAL (SM_HW + HALF_PTS * 2)    // 48 KB

__device__ float g_vmin[2 * BBATCH * SPLIT * NPTS];
__device__ int   g_vidx[2 * BBATCH * SPLIT * NPTS];
__device__ unsigned int g_pair[NPAIRS];
__device__ float g_partials[NPAIRS];
__device__ unsigned int g_done = 0;

__device__ __forceinline__ float ldcg_f(const float* p) {
    float v; asm volatile("ld.global.cg.f32 %0, [%1];" : "=f"(v) : "l"(p)); return v;
}
__device__ __forceinline__ int ldcg_i(const int* p) {
    int v; asm volatile("ld.global.cg.s32 %0, [%1];" : "=r"(v) : "l"(p)); return v;
}

// blockIdx.x = tile*SPLIT + half (0..3), y = batch, z = dir.
__global__ __launch_bounds__(THREADS, 1)
void chamfer_h2_kernel(const float* __restrict__ kp1,
                       const float* __restrict__ kp2,
                       const float* __restrict__ sig1,
                       const float* __restrict__ sig2,
                       float* __restrict__ out)
{
    const int tile = blockIdx.x >> 1;
    const int half = blockIdx.x & 1;
    const int b    = blockIdx.y;
    const int dir  = blockIdx.z;
    const float* qk = dir ? kp2 : kp1;
    const float* tk = dir ? kp1 : kp2;

    extern __shared__ char smem[];
    float*  sx = (float*)(smem + SM_SX);
    float*  sy = (float*)(smem + SM_SY);
    float*  sz = (float*)(smem + SM_SZ);
    float*  sw = (float*)(smem + SM_SW);
    __half* hx = (__half*)(smem + SM_HX);
    __half* hy = (__half*)(smem + SM_HY);
    __half* hz = (__half*)(smem + SM_HZ);
    __half* hw = (__half*)(smem + SM_HW);

    __shared__ float s_pcap, s_wcap;
    if (threadIdx.x == 0) { s_pcap = 0.0f; s_wcap = 0.0f; }
    __syncthreads();

    {   // fill both SoAs; track block maxima for the error bound
        const float* tp = tk + (size_t)b * 3 * NPTS + half * HALF_PTS;
        float lpc = 0.0f, lwc = 0.0f;
        for (int i = threadIdx.x; i < HALF_PTS; i += THREADS) {
            float x = tp[i];
            float y = tp[NPTS + i];
            float z = tp[2 * NPTS + i];
            float w = fmaf(x, x, fmaf(y, y, z * z));
            sx[i] = x; sy[i] = y; sz[i] = z; sw[i] = w;
            hx[i] = __float2half_rn(x);
            hy[i] = __float2half_rn(y);
            hz[i] = __float2half_rn(z);
            hw[i] = __float2half_rn(w);
            lpc = fmaxf(lpc, fmaxf(fabsf(x), fmaxf(fabsf(y), fabsf(z))));
            lwc = fmaxf(lwc, w);
        }
        atomicMax((int*)&s_pcap, __float_as_int(lpc));  // floats >= 0: int order ok
        atomicMax((int*)&s_wcap, __float_as_int(lwc));
    }
    __syncthreads();
    const float pcap = s_pcap, wcap = s_wcap;

    const float* qp = qk + (size_t)b * 3 * NPTS;
    const int row0 = tile * ROWS_PER_BLOCK + threadIdx.x;
    const float INF = __int_as_float(0x7f800000);

    __half2 nx2[RPT], ny2[RPT], nz2[RPT];
    float   best[RPT], Mt[RPT];
    uint32_t mask[RPT];

    #pragma unroll
    for (int r = 0; r < RPT; r++) {
        const int m = row0 + r * THREADS;
        float x = qp[m], y = qp[NPTS + m], z = qp[2 * NPTS + m];
        nx2[r] = __half2half2(__float2half_rn(-2.0f * x));
        ny2[r] = __half2half2(__float2half_rn(-2.0f * y));
        nz2[r] = __half2half2(__float2half_rn(-2.0f * z));
        float S = fabsf(x) + fabsf(y) + fabsf(z);
        // fp16 error bound: input conversions + 3 chained roundings, all
        // O(2^-11 x |v|max); factor ~4 slack + covers the 2x flag logic.
        Mt[r]   = 0.03f + 0.004f * (wcap + 2.0f * S * pcap);
        best[r] = INF;
        mask[r] = 0u;
    }

    // Candidate pass: fp16 v = w - 2a.p, group-min, margin-flag groups.
    const uint4* hxv = (const uint4*)hx;   // 8 targets per uint4
    const uint4* hyv = (const uint4*)hy;
    const uint4* hzv = (const uint4*)hz;
    const uint4* hwv = (const uint4*)hw;
    const __half2 INF2 = __float2half2_rn(65504.0f);

    for (int g = 0; g < NGROUPS; g++) {
        __half2 gm[RPT];
        #pragma unroll
        for (int r = 0; r < RPT; r++) gm[r] = INF2;

        const int t0 = g * (GSIZE / 8);
        #pragma unroll 2
        for (int t = 0; t < GSIZE / 8; t++) {
            uint4 X = hxv[t0 + t];
            uint4 Y = hyv[t0 + t];
            uint4 Z = hzv[t0 + t];
            uint4 W = hwv[t0 + t];
            const __half2* xp = (const __half2*)&X;
            const __half2* yp = (const __half2*)&Y;
            const __half2* zp = (const __half2*)&Z;
            const __half2* wp = (const __half2*)&W;
            #pragma unroll
            for (int q = 0; q < 4; q++) {
                #pragma unroll
                for (int r = 0; r < RPT; r++) {
                    __half2 v = __hfma2(nx2[r], xp[q],
                                __hfma2(ny2[r], yp[q],
                                __hfma2(nz2[r], zp[q], wp[q])));
                    gm[r] = __hmin2(gm[r], v);
                }
            }
        }
        #pragma unroll
        for (int r = 0; r < RPT; r++) {
            float gmf = fminf(__low2float(gm[r]), __high2float(gm[r]));
            if (gmf <= best[r] + Mt[r]) mask[r] |= (1u << g);
            best[r] = fminf(best[r], gmf);
        }
    }

    // Exact fp32 replay of flagged groups (ascending -> exact first-argmin).
    const size_t sb = (((size_t)(dir * BBATCH + b)) * SPLIT + half) * NPTS;
    #pragma unroll
    for (int r = 0; r < RPT; r++) {
        const int m = row0 + r * THREADS;
        float nx = -2.0f * qp[m];
        float ny = -2.0f * qp[NPTS + m];
        float nz = -2.0f * qp[2 * NPTS + m];
        float vb = INF;
        int   bi = 0;
        uint32_t mk = mask[r];
        while (mk) {
            int gsel = __ffs(mk) - 1;
            mk &= mk - 1;
            const int base = gsel * GSIZE;
            #pragma unroll 4
            for (int k = 0; k < GSIZE; k++) {
                const int n = base + k;
                float v = fmaf(nx, sx[n], fmaf(ny, sy[n], fmaf(nz, sz[n], sw[n])));
                bi = (v < vb) ? n : bi;      // strict < keeps first index
                vb = fminf(vb, v);
            }
        }
        g_vmin[sb + m] = vb;
        g_vidx[sb + m] = bi + half * HALF_PTS;
    }

    // Pair rendezvous: second finisher merges halves and computes the loss.
    const int pair_id = (dir * BBATCH + b) * ROW_TILES + tile;
    __shared__ int s_second;
    __threadfence();
    __syncthreads();
    if (threadIdx.x == 0)
        s_second = (atomicAdd(&g_pair[pair_id], 1u) == 1);
    __syncthreads();
    if (!s_second) return;
    __threadfence();

    const size_t pm  = (((size_t)(dir * BBATCH + b)) * SPLIT) * NPTS;  // half0
    const size_t pm1 = pm + NPTS;                                      // half1
    float acc = 0.0f;
    const float* qs = (dir ? sig2 : sig1) + (size_t)b * NPTS;
    const float* ts = (dir ? sig1 : sig2) + (size_t)b * NPTS;
    #pragma unroll
    for (int r = 0; r < RPT; r++) {
        const int m = row0 + r * THREADS;
        float v0 = ldcg_f(g_vmin + pm + m);
        int   i0 = ldcg_i(g_vidx + pm + m);
        float v1 = ldcg_f(g_vmin + pm1 + m);
        int   i1 = ldcg_i(g_vidx + pm1 + m);
        bool use0 = (v0 <= v1);              // tie -> half0 (lower index first)
        float vmin = use0 ? v0 : v1;
        int   bi   = use0 ? i0 : i1;

        float x = qp[m], y = qp[NPTS + m], z = qp[2 * NPTS + m];
        float sqa = fmaf(x, x, fmaf(y, y, z * z));
        float d2  = vmin + sqa;
        float mind = sqrtf(fmaxf(d2, EPSF));
        float sg = 0.5f * (qs[m] + ts[bi]);
        acc += logf(sg) + mind / sg;
    }

    // Block reduction -> per-pair partial (fixed order, deterministic).
    __shared__ float red[THREADS];
    __shared__ int   s_last;
    red[threadIdx.x] = acc;
    __syncthreads();
    #pragma unroll
    for (int s = THREADS / 2; s > 32; s >>= 1) {
        if (threadIdx.x < s) red[threadIdx.x] += red[threadIdx.x + s];
        __syncthreads();
    }
    if (threadIdx.x < 32) {
        float v = red[threadIdx.x] + red[threadIdx.x + 32];
        #pragma unroll
        for (int o = 16; o > 0; o >>= 1)
            v += __shfl_down_sync(0xffffffffu, v, o);
        if (threadIdx.x == 0) {
            g_partials[pair_id] = v;
            g_pair[pair_id] = 0;             // reset for next graph replay
            __threadfence();
            unsigned int old = atomicAdd(&g_done, 1u);
            s_last = (old == NPAIRS - 1);
        }
    }
    __syncthreads();

    if (s_last) {                            // fold the 64 partials
        __threadfence();
        __shared__ double dred[NPAIRS];
        if (threadIdx.x < NPAIRS)
            dred[threadIdx.x] = (double)ldcg_f(g_partials + threadIdx.x);
        __syncthreads();
        for (int s = NPAIRS / 2; s > 0; s >>= 1) {
            if (threadIdx.x < s) dred[threadIdx.x] += dred[threadIdx.x + s];
            __syncthreads();
        }
        if (threadIdx.x == 0) {
            out[0] = (float)(dred[0] * (1.0 / ((double)BBATCH * (double)NPTS)));
            g_done = 0;                      // reset for next graph replay
        }
    }
}

extern "C" void kernel_launch(void* const* d_in, const int* in_sizes, int n_in,
                              void* d_out, int out_size)
{
    (void)in_sizes; (void)n_in; (void)out_size;
    const float* kp1  = (const float*)d_in[0];  // [B, 3, M]
    const float* kp2  = (const float*)d_in[1];  // [B, 3, N]
    const float* sig1 = (const float*)d_in[2];  // [B, M]
    const float* sig2 = (const float*)d_in[3];  // [B, N]
    float* out = (float*)d_out;

    cudaFuncSetAttribute(chamfer_h2_kernel,
                         cudaFuncAttributeMaxDynamicSharedMemorySize, SM_TOTAL);

    dim3 grid(ROW_TILES * SPLIT, BBATCH, 2);    // 4 x 16 x 2 = 128 blocks
    chamfer_h2_kernel<<<grid, THREADS, SM_TOTAL>>>(kp1, kp2, sig1, sig2, out);
}

// round 16
// speedup vs baseline: 6.9756x; 6.9756x over previous
#include <cuda_runtime.h>
#include <math.h>
#include <stdint.h>

#define BBATCH 16
#define NPTS   4096
#define THREADS 512
#define RPT 4
#define SPLIT 2
#define HALF_PTS (NPTS / SPLIT)            // 2048 targets per block (32 KB)
#define ROWS_PER_BLOCK (THREADS * RPT)     // 2048
#define ROW_TILES (NPTS / ROWS_PER_BLOCK)  // 2
#define NPAIRS (2 * BBATCH * ROW_TILES)    // 64 merge pairs
#define GSIZE 32
#define NGROUPS (HALF_PTS / GSIZE)         // 64
#define EPSF 1e-12f

// Scratch: per (dir,b,half,row): v-domain min and absolute argmin index.
__device__ float g_vmin[2 * BBATCH * SPLIT * NPTS];
__device__ int   g_vidx[2 * BBATCH * SPLIT * NPTS];
__device__ unsigned int g_pair[NPAIRS];    // zero-init; self-resetting
__device__ float g_partials[NPAIRS];
__device__ unsigned int g_done = 0;

__device__ __forceinline__ uint64_t pack2(float lo, float hi) {
    uint64_t r;
    asm("mov.b64 %0, {%1,%2};" : "=l"(r) : "f"(lo), "f"(hi));
    return r;
}
__device__ __forceinline__ uint64_t fma2(uint64_t a, uint64_t b, uint64_t c) {
    uint64_t d;
    asm("fma.rn.f32x2 %0, %1, %2, %3;" : "=l"(d) : "l"(a), "l"(b), "l"(c));
    return d;
}
// Zero-cost unpack: pure value reinterprets (sub-register naming for ptxas).
__device__ __forceinline__ void unpack64(uint64_t v, float& lo, float& hi) {
    double d = __longlong_as_double((long long)v);
    lo = __int_as_float(__double2loint(d));
    hi = __int_as_float(__double2hiint(d));
}
__device__ __forceinline__ float ldcg_f(const float* p) {
    float v; asm volatile("ld.global.cg.f32 %0, [%1];" : "=f"(v) : "l"(p)); return v;
}
__device__ __forceinline__ int ldcg_i(const int* p) {
    int v; asm volatile("ld.global.cg.s32 %0, [%1];" : "=r"(v) : "l"(p)); return v;
}

// blockIdx.x = tile*SPLIT + half  (0..3), y = batch, z = dir.
__global__ __launch_bounds__(THREADS, 1)
void chamfer_fused_kernel(const float* __restrict__ kp1,
                          const float* __restrict__ kp2,
                          const float* __restrict__ sig1,
                          const float* __restrict__ sig2,
                          float* __restrict__ out)
{
    const int tile = blockIdx.x >> 1;
    const int half = blockIdx.x & 1;
    const int b    = blockIdx.y;
    const int dir  = blockIdx.z;
    const float* qk = dir ? kp2 : kp1;
    const float* tk = dir ? kp1 : kp2;

    // +4 floats padding so the final (dead) prefetch stays in-bounds.
    __shared__ __align__(16) float sx[HALF_PTS + 4];
    __shared__ __align__(16) float sy[HALF_PTS + 4];
    __shared__ __align__(16) float sz[HALF_PTS + 4];
    __shared__ __align__(16) float sw[HALF_PTS + 4];

    {   // load this half of the target set (coalesced per plane)
        const float* tp = tk + (size_t)b * 3 * NPTS + half * HALF_PTS;
        for (int i = threadIdx.x; i < HALF_PTS; i += THREADS) {
            float x = tp[i];
            float y = tp[NPTS + i];
            float z = tp[2 * NPTS + i];
            sx[i] = x; sy[i] = y; sz[i] = z;
            sw[i] = fmaf(x, x, fmaf(y, y, z * z));
        }
        if (threadIdx.x < 4) {  // init padding (never used in results)
            sx[HALF_PTS + threadIdx.x] = 0.0f;
            sy[HALF_PTS + threadIdx.x] = 0.0f;
            sz[HALF_PTS + threadIdx.x] = 0.0f;
            sw[HALF_PTS + threadIdx.x] = 0.0f;
        }
    }
    __syncthreads();

    const float* qp = qk + (size_t)b * 3 * NPTS;
    const int row0 = tile * ROWS_PER_BLOCK + threadIdx.x;
    uint64_t ax2[RPT], ay2[RPT], az2[RPT];
    float    best[RPT];
    int      bg[RPT];

    #pragma unroll
    for (int r = 0; r < RPT; r++) {
        const int m = row0 + r * THREADS;
        float x = qp[m], y = qp[NPTS + m], z = qp[2 * NPTS + m];
        ax2[r] = pack2(-2.0f * x, -2.0f * x);
        ay2[r] = pack2(-2.0f * y, -2.0f * y);
        az2[r] = pack2(-2.0f * z, -2.0f * z);
        best[r] = __int_as_float(0x7f800000);   // +inf
        bg[r] = 0;
    }
    const float INF = __int_as_float(0x7f800000);

    // v = ||p||^2 - 2 a.p (same argmin as d^2). Software-pipelined double-
    // buffered A/B register tiles hide the ~29-cyc LDS latency; packed FMA
    // chains end in value-reinterpret unpacks (no SASS movs). Winning
    // 32-group replayed afterwards for the exact first-argmin index.
    ulonglong2 XA = *(const ulonglong2*)(sx);
    ulonglong2 YA = *(const ulonglong2*)(sy);
    ulonglong2 ZA = *(const ulonglong2*)(sz);
    ulonglong2 WA = *(const ulonglong2*)(sw);

    for (int g = 0; g < NGROUPS; g++) {
        float c1[RPT], c2[RPT];
        #pragma unroll
        for (int r = 0; r < RPT; r++) { c1[r] = INF; c2[r] = INF; }

        const int base = g * GSIZE;
        #pragma unroll
        for (int kk = 0; kk < GSIZE; kk += 8) {
            const int nB = base + kk + 4;
            ulonglong2 XB = *(const ulonglong2*)(sx + nB);
            ulonglong2 YB = *(const ulonglong2*)(sy + nB);
            ulonglong2 ZB = *(const ulonglong2*)(sz + nB);
            ulonglong2 WB = *(const ulonglong2*)(sw + nB);
            #pragma unroll
            for (int r = 0; r < RPT; r++) {
                float l0, h0, l1, h1;
                unpack64(fma2(ax2[r], XA.x,
                         fma2(ay2[r], YA.x, fma2(az2[r], ZA.x, WA.x))), l0, h0);
                unpack64(fma2(ax2[r], XA.y,
                         fma2(ay2[r], YA.y, fma2(az2[r], ZA.y, WA.y))), l1, h1);
                c1[r] = fminf(c1[r], fminf(l0, h0));
                c2[r] = fminf(c2[r], fminf(l1, h1));
            }
            const int nA = base + kk + 8;   // crosses group boundary / padding
            XA = *(const ulonglong2*)(sx + nA);
            YA = *(const ulonglong2*)(sy + nA);
            ZA = *(const ulonglong2*)(sz + nA);
            WA = *(const ulonglong2*)(sw + nA);
            #pragma unroll
            for (int r = 0; r < RPT; r++) {
                float l0, h0, l1, h1;
                unpack64(fma2(ax2[r], XB.x,
                         fma2(ay2[r], YB.x, fma2(az2[r], ZB.x, WB.x))), l0, h0);
                unpack64(fma2(ax2[r], XB.y,
                         fma2(ay2[r], YB.y, fma2(az2[r], ZB.y, WB.y))), l1, h1);
                c1[r] = fminf(c1[r], fminf(l0, h0));
                c2[r] = fminf(c2[r], fminf(l1, h1));
            }
        }
        #pragma unroll
        for (int r = 0; r < RPT; r++) {
            float gm = fminf(c1[r], c2[r]);
            bg[r]   = (gm < best[r]) ? g : bg[r];   // strict < -> earliest group
            best[r] = fminf(best[r], gm);
        }
    }

    // Replay winning group (identical scalar FMA chain -> exact first index).
    int bidx[RPT];
    #pragma unroll
    for (int r = 0; r < RPT; r++) {
        const int m = row0 + r * THREADS;
        float nx = -2.0f * qp[m];
        float ny = -2.0f * qp[NPTS + m];
        float nz = -2.0f * qp[2 * NPTS + m];
        const int base = bg[r] * GSIZE;
        float lb = INF;
        int   bi = base;
        #pragma unroll 4
        for (int k = 0; k < GSIZE; k++) {
            const int n = base + k;
            float v = fmaf(nx, sx[n], fmaf(ny, sy[n], fmaf(nz, sz[n], sw[n])));
            bi = (v < lb) ? n : bi;                 // strict < keeps first index
            lb = fminf(lb, v);
        }
        bidx[r] = bi + half * HALF_PTS;             // absolute target index
    }

    // Publish this half's results.
    const size_t sb = (((size_t)(dir * BBATCH + b)) * SPLIT + half) * NPTS;
    #pragma unroll
    for (int r = 0; r < RPT; r++) {
        const int m = row0 + r * THREADS;
        g_vmin[sb + m] = best[r];
        g_vidx[sb + m] = bidx[r];
    }

    // Pair rendezvous: second finisher merges halves and computes the loss.
    const int pair_id = (dir * BBATCH + b) * ROW_TILES + tile;
    __shared__ int s_second;
    __threadfence();
    __syncthreads();
    if (threadIdx.x == 0)
        s_second = (atomicAdd(&g_pair[pair_id], 1u) == 1);
    __syncthreads();
    if (!s_second) return;
    __threadfence();

    // Read peer half's results (L2, bypass non-coherent L1).
    const size_t po = (((size_t)(dir * BBATCH + b)) * SPLIT + (half ^ 1)) * NPTS;
    float acc = 0.0f;
    const float* qs = (dir ? sig2 : sig1) + (size_t)b * NPTS;
    const float* ts = (dir ? sig1 : sig2) + (size_t)b * NPTS;
    #pragma unroll
    for (int r = 0; r < RPT; r++) {
        const int m = row0 + r * THREADS;
        float vo = ldcg_f(g_vmin + po + m);
        int   io = ldcg_i(g_vidx + po + m);
        // half0 wins ties (lower absolute index = first occurrence)
        float v0 = half ? vo : best[r];
        int   i0 = half ? io : bidx[r];
        float v1 = half ? best[r] : vo;
        int   i1 = half ? bidx[r] : io;
        bool use0 = (v0 <= v1);
        float vmin = use0 ? v0 : v1;
        int   bi   = use0 ? i0 : i1;

        float x = qp[m], y = qp[NPTS + m], z = qp[2 * NPTS + m];
        float sqa = fmaf(x, x, fmaf(y, y, z * z));
        float d2   = vmin + sqa;
        float mind = sqrtf(fmaxf(d2, EPSF));
        float sg   = 0.5f * (qs[m] + ts[bi]);
        acc += logf(sg) + mind / sg;
    }

    // Block reduction -> per-pair partial (fixed order -> deterministic,
    // identical whichever block of the pair runs it).
    __shared__ float red[THREADS];
    __shared__ int   s_last;
    red[threadIdx.x] = acc;
    __syncthreads();
    #pragma unroll
    for (int s = THREADS / 2; s > 32; s >>= 1) {
        if (threadIdx.x < s) red[threadIdx.x] += red[threadIdx.x + s];
        __syncthreads();
    }
    if (threadIdx.x < 32) {
        float v = red[threadIdx.x] + red[threadIdx.x + 32];
        #pragma unroll
        for (int o = 16; o > 0; o >>= 1)
            v += __shfl_down_sync(0xffffffffu, v, o);
        if (threadIdx.x == 0) {
            g_partials[pair_id] = v;
            g_pair[pair_id] = 0;            // reset for next graph replay
            __threadfence();
            unsigned int old = atomicAdd(&g_done, 1u);
            s_last = (old == NPAIRS - 1);
        }
    }
    __syncthreads();

    // Last pair-merger folds the 64 partials (fixed-order tree).
    if (s_last) {
        __threadfence();
        __shared__ double dred[NPAIRS];
        if (threadIdx.x < NPAIRS)
            dred[threadIdx.x] = (double)ldcg_f(g_partials + threadIdx.x);
        __syncthreads();
        for (int s = NPAIRS / 2; s > 0; s >>= 1) {
            if (threadIdx.x < s) dred[threadIdx.x] += dred[threadIdx.x + s];
            __syncthreads();
        }
        if (threadIdx.x == 0) {
            out[0] = (float)(dred[0] * (1.0 / ((double)BBATCH * (double)NPTS)));
            g_done = 0;                     // reset for next graph replay
        }
    }
}

extern "C" void kernel_launch(void* const* d_in, const int* in_sizes, int n_in,
                              void* d_out, int out_size)
{
    (void)in_sizes; (void)n_in; (void)out_size;
    const float* kp1  = (const float*)d_in[0];  // [B, 3, M]
    const float* kp2  = (const float*)d_in[1];  // [B, 3, N]
    const float* sig1 = (const float*)d_in[2];  // [B, M]
    const float* sig2 = (const float*)d_in[3];  // [B, N]
    float* out = (float*)d_out;

    dim3 grid(ROW_TILES * SPLIT, BBATCH, 2);    // 4 x 16 x 2 = 128 blocks
    chamfer_fused_kernel<<<grid, THREADS>>>(kp1, kp2, sig1, sig2, out);
}